// round 4
// baseline (speedup 1.0000x reference)
#include <cuda_runtime.h>

#define NA   768
#define NM1  767
#define NE   (768*767)      // 589056
#define DIM  64
#define NCV  50
#define NCONV 3

#define CONV_THREADS 128
#define CHUNK  16
#define SPLITS 48           // CHUNK*SPLITS == NA

// ---------------- scratch (__device__ globals; no runtime allocation) ----------
__device__ float g_rbfT[NCV * NE];   // transposed rbf: [k][e], ~118 MB
__device__ float g_h  [NA * DIM];
__device__ float g_nw [NA * DIM];
__device__ float g_agg[NA * DIM];
__device__ float g_ha [NA];

// softplus_bt(x, beta=0.5, thr=14): bx=0.5x; bx>14 ? x : softplus(bx)/0.5
__device__ __forceinline__ float softplus_half(float x) {
    float t = 0.5f * x;
    if (t > 14.0f) return x;
    return 2.0f * (fmaxf(t, 0.0f) + log1pf(__expf(-fabsf(t))));
}

// ---------------- h init: embedding gather -----------------------------------
__global__ void k_init_h(const int* __restrict__ at, const float* __restrict__ emb) {
    int idx = blockIdx.x * blockDim.x + threadIdx.x;
    if (idx < NA * DIM) {
        int i = idx >> 6;
        int c = idx & 63;
        g_h[idx] = emb[at[i] * DIM + c];
    }
}

// ---------------- rbf: exp(-(1/gap)*(d-mu_k)^2), stored transposed ------------
__global__ void k_rbf(const float* __restrict__ dist) {
    int e = blockIdx.x * blockDim.x + threadIdx.x;
    if (e >= NE) return;
    float d = dist[e];
#pragma unroll
    for (int k = 0; k < NCV; k++) {
        float mu = (float)(k * (5.0 / 49.0));
        float v = d - mu;
        g_rbfT[k * NE + e] = __expf(-9.8f * v * v);
    }
}

// ---------------- nw = h @ w1[l]; also zero agg -------------------------------
__global__ void k_nw(const float* __restrict__ w1l) {
    __shared__ float hrow[DIM];
    int i = blockIdx.x, c = threadIdx.x;
    hrow[c] = g_h[i * DIM + c];
    __syncthreads();
    float s = 0.0f;
#pragma unroll
    for (int k = 0; k < DIM; k++) s += hrow[k] * w1l[k * DIM + c];
    g_nw[i * DIM + c]  = s;
    g_agg[i * DIM + c] = 0.0f;
}

// ---------------- fused conv edge kernel (dst-major, register agg) ------------
// block: 128 threads, thread t owns dst j = blockIdx.x*128+t
// blockIdx.y selects a src chunk of CHUNK atoms; partial agg atomically added.
__global__ void __launch_bounds__(CONV_THREADS, 2)
k_conv(const float* __restrict__ pw1l, const float* __restrict__ pb1l,
       const float* __restrict__ pw2l, const float* __restrict__ pb2l) {
    extern __shared__ float sm[];
    float* s_pw1 = sm;               // 50*64 = 3200
    float* s_pw2 = sm + 3200;        // 64*64 = 4096
    float* s_pb1 = sm + 7296;        // 64
    float* s_pb2 = sm + 7360;        // 64
    float* s_t   = sm + 7424;        // 64*128 (per-thread t slice, [k][tid])

    int tid = threadIdx.x;
    for (int idx = tid; idx < 3200; idx += CONV_THREADS) s_pw1[idx] = pw1l[idx];
    for (int idx = tid; idx < 4096; idx += CONV_THREADS) s_pw2[idx] = pw2l[idx];
    if (tid < DIM) { s_pb1[tid] = pb1l[tid]; s_pb2[tid] = pb2l[tid]; }
    __syncthreads();

    int j  = blockIdx.x * CONV_THREADS + tid;
    int i0 = blockIdx.y * CHUNK;

    float acc[DIM];
#pragma unroll
    for (int c = 0; c < DIM; c++) acc[c] = 0.0f;

    for (int ii = 0; ii < CHUNK; ii++) {
        int i = i0 + ii;
        if (i == j) continue;
        int eidx = i * NM1 + j - (j > i ? 1 : 0);

        // u = rbf(e) @ pw1 + pb1   (K=50)
        float u[DIM];
#pragma unroll
        for (int c = 0; c < DIM; c++) u[c] = s_pb1[c];
#pragma unroll 2
        for (int k = 0; k < NCV; k++) {
            float rk = g_rbfT[k * NE + eidx];            // coalesced across tid
            const float4* w4 = (const float4*)(s_pw1 + k * DIM);
#pragma unroll
            for (int c4 = 0; c4 < 16; c4++) {
                float4 w = w4[c4];
                u[4*c4+0] += rk * w.x;
                u[4*c4+1] += rk * w.y;
                u[4*c4+2] += rk * w.z;
                u[4*c4+3] += rk * w.w;
            }
        }
        // softplus -> private smem slice (lets 2nd GEMM index k dynamically)
#pragma unroll
        for (int c = 0; c < DIM; c++) {
            float x = u[c];
            float t = 0.5f * x;
            float sp = (t > 14.0f) ? x
                     : 2.0f * (fmaxf(t, 0.0f) + log1pf(__expf(-fabsf(t))));
            s_t[c * CONV_THREADS + tid] = sp;
        }
        // e = t @ pw2 + pb2   (K=64)
        float ev[DIM];
#pragma unroll
        for (int c = 0; c < DIM; c++) ev[c] = s_pb2[c];
#pragma unroll 2
        for (int k = 0; k < DIM; k++) {
            float tk = s_t[k * CONV_THREADS + tid];      // conflict-free
            const float4* w4 = (const float4*)(s_pw2 + k * DIM);
#pragma unroll
            for (int c4 = 0; c4 < 16; c4++) {
                float4 w = w4[c4];
                ev[4*c4+0] += tk * w.x;
                ev[4*c4+1] += tk * w.y;
                ev[4*c4+2] += tk * w.z;
                ev[4*c4+3] += tk * w.w;
            }
        }
        // acc += nw[i] * e   (nw[i] broadcast across block)
        const float4* nw4 = (const float4*)(g_nw + i * DIM);
#pragma unroll
        for (int c4 = 0; c4 < 16; c4++) {
            float4 nv = nw4[c4];
            acc[4*c4+0] += nv.x * ev[4*c4+0];
            acc[4*c4+1] += nv.y * ev[4*c4+1];
            acc[4*c4+2] += nv.z * ev[4*c4+2];
            acc[4*c4+3] += nv.w * ev[4*c4+3];
        }
    }
#pragma unroll
    for (int c = 0; c < DIM; c++) atomicAdd(&g_agg[j * DIM + c], acc[c]);
}

// ---------------- update MLP: h += softplus(agg@qw1+qb1)@qw2+qb2 --------------
__global__ void k_update(const float* __restrict__ qw1l, const float* __restrict__ qb1l,
                         const float* __restrict__ qw2l, const float* __restrict__ qb2l) {
    __shared__ float arow[DIM];
    __shared__ float trow[DIM];
    int i = blockIdx.x, c = threadIdx.x;
    arow[c] = g_agg[i * DIM + c];
    __syncthreads();
    float s = qb1l[c];
#pragma unroll
    for (int k = 0; k < DIM; k++) s += arow[k] * qw1l[k * DIM + c];
    trow[c] = softplus_half(s);
    __syncthreads();
    float s2 = qb2l[c];
#pragma unroll
    for (int k = 0; k < DIM; k++) s2 += trow[k] * qw2l[k * DIM + c];
    g_h[i * DIM + c] += s2;
}

// ---------------- atom update: ha (N,1) ---------------------------------------
__global__ void k_atom(const float* __restrict__ au_w1, const float* __restrict__ au_b1,
                       const float* __restrict__ au_w2, const float* __restrict__ au_b2) {
    __shared__ float hrow[DIM];
    __shared__ float red[DIM];
    int i = blockIdx.x, c = threadIdx.x;
    hrow[c] = g_h[i * DIM + c];
    __syncthreads();
    float s = au_b1[c];
#pragma unroll
    for (int k = 0; k < DIM; k++) s += hrow[k] * au_w1[k * DIM + c];
    // ShiftSoftplus: softplus_bt(x,1,20) - ln2
    float sp = (s > 20.0f) ? s : (fmaxf(s, 0.0f) + log1pf(__expf(-fabsf(s))));
    sp -= 0.69314718055994530942f;
    red[c] = sp * au_w2[c];
    __syncthreads();
    if (c < 32) {
        float v = red[c] + red[c + 32];
#pragma unroll
        for (int off = 16; off; off >>= 1) v += __shfl_down_sync(0xffffffffu, v, off);
        if (c == 0) g_ha[i] = v + au_b2[0];
    }
}

// ---------------- readout over all ordered pairs ------------------------------
__global__ void __launch_bounds__(128)
k_readout(const float* __restrict__ ro_w1, const float* __restrict__ ro_b1,
          const float* __restrict__ ro_w2, const float* __restrict__ ro_b2,
          float* __restrict__ out) {
    __shared__ float s_w1[52 * DIM];   // rows: 0=ha_src, 1=ha_dst, 2..51=rbf
    __shared__ float s_b1[DIM];
    __shared__ float s_w2[DIM * 2];
    __shared__ float s_b2[2];
    int tid = threadIdx.x;
    for (int idx = tid; idx < 52 * DIM; idx += 128) s_w1[idx] = ro_w1[idx];
    if (tid < DIM)     s_b1[tid] = ro_b1[tid];
    if (tid < DIM * 2) s_w2[tid] = ro_w2[tid];
    if (tid < 2)       s_b2[tid] = ro_b2[tid];
    __syncthreads();

    int e = blockIdx.x * 128 + tid;
    if (e >= NE) return;
    int i   = e / NM1;
    int pos = e - i * NM1;
    int j   = pos + (pos >= i ? 1 : 0);
    float hi = g_ha[i], hj = g_ha[j];

    float f[DIM];
#pragma unroll
    for (int c = 0; c < DIM; c++) f[c] = s_b1[c];
    {
        const float4* wa = (const float4*)(s_w1);
        const float4* wb = (const float4*)(s_w1 + DIM);
#pragma unroll
        for (int c4 = 0; c4 < 16; c4++) {
            float4 a = wa[c4], b = wb[c4];
            f[4*c4+0] += hi * a.x + hj * b.x;
            f[4*c4+1] += hi * a.y + hj * b.y;
            f[4*c4+2] += hi * a.z + hj * b.z;
            f[4*c4+3] += hi * a.w + hj * b.w;
        }
    }
#pragma unroll 2
    for (int k = 0; k < NCV; k++) {
        float rk = g_rbfT[k * NE + e];                 // coalesced
        const float4* w4 = (const float4*)(s_w1 + (2 + k) * DIM);
#pragma unroll
        for (int c4 = 0; c4 < 16; c4++) {
            float4 w = w4[c4];
            f[4*c4+0] += rk * w.x;
            f[4*c4+1] += rk * w.y;
            f[4*c4+2] += rk * w.z;
            f[4*c4+3] += rk * w.w;
        }
    }
    float l0 = s_b2[0], l1 = s_b2[1];
#pragma unroll
    for (int c = 0; c < DIM; c++) {
        float v = fmaxf(f[c], 0.0f);                   // relu
        l0 += v * s_w2[c * 2 + 0];
        l1 += v * s_w2[c * 2 + 1];
    }
    float m  = fmaxf(l0, l1);
    float p0 = __expf(l0 - m), p1 = __expf(l1 - m);
    float inv = 1.0f / (p0 + p1);
    out[2 * e + 0] = p0 * inv;
    out[2 * e + 1] = p1 * inv;
}

// ---------------- launch ------------------------------------------------------
extern "C" void kernel_launch(void* const* d_in, const int* in_sizes, int n_in,
                              void* d_out, int out_size) {
    const int*   at    = (const int*)  d_in[0];
    const float* dist  = (const float*)d_in[1];
    // d_in[2]=src, d_in[3]=dst: implied by complete-graph closed form, unused
    const float* emb   = (const float*)d_in[4];
    const float* w1    = (const float*)d_in[5];
    const float* pw1   = (const float*)d_in[6];
    const float* pb1   = (const float*)d_in[7];
    const float* pw2   = (const float*)d_in[8];
    const float* pb2   = (const float*)d_in[9];
    const float* qw1   = (const float*)d_in[10];
    const float* qb1   = (const float*)d_in[11];
    const float* qw2   = (const float*)d_in[12];
    const float* qb2   = (const float*)d_in[13];
    const float* au_w1 = (const float*)d_in[14];
    const float* au_b1 = (const float*)d_in[15];
    const float* au_w2 = (const float*)d_in[16];
    const float* au_b2 = (const float*)d_in[17];
    const float* ro_w1 = (const float*)d_in[18];
    const float* ro_b1 = (const float*)d_in[19];
    const float* ro_w2 = (const float*)d_in[20];
    const float* ro_b2 = (const float*)d_in[21];
    float* out = (float*)d_out;

    const int conv_smem = (3200 + 4096 + 64 + 64 + 64 * CONV_THREADS) * (int)sizeof(float);
    cudaFuncSetAttribute(k_conv, cudaFuncAttributeMaxDynamicSharedMemorySize, conv_smem);

    k_init_h<<<(NA * DIM + 255) / 256, 256>>>(at, emb);
    k_rbf<<<(NE + 255) / 256, 256>>>(dist);

    for (int l = 0; l < NCONV; l++) {
        k_nw<<<NA, DIM>>>(w1 + l * DIM * DIM);
        dim3 grid(NA / CONV_THREADS, SPLITS);
        k_conv<<<grid, CONV_THREADS, conv_smem>>>(pw1 + l * NCV * DIM, pb1 + l * DIM,
                                                  pw2 + l * DIM * DIM, pb2 + l * DIM);
        k_update<<<NA, DIM>>>(qw1 + l * DIM * DIM, qb1 + l * DIM,
                              qw2 + l * DIM * DIM, qb2 + l * DIM);
    }
    k_atom<<<NA, DIM>>>(au_w1, au_b1, au_w2, au_b2);
    k_readout<<<(NE + 127) / 128, 128>>>(ro_w1, ro_b1, ro_w2, ro_b2, out);
}

// round 6
// speedup vs baseline: 4.3428x; 4.3428x over previous
#include <cuda_runtime.h>
#include <cstdint>

#define NA    768
#define NM1   767
#define NE    (768*767)      // 589056
#define DIM   64
#define NCONV 3
#define GAPF  0.10204081632653061f   // 5/49

// ---------------- device scratch ----------------
__device__ float g_h    [NA * DIM];
__device__ float g_nw   [NA * DIM];
__device__ float g_agg  [NA * DIM];
__device__ float g_nwsum[DIM];
__device__ float g_ha   [NA];

// ---------------- tf32 helpers ----------------
__device__ __forceinline__ uint32_t f2tf(float x) {
    uint32_t u; asm("cvt.rna.tf32.f32 %0, %1;" : "=r"(u) : "f"(x)); return u;
}
__device__ __forceinline__ float f2tf_f(float x) { return __uint_as_float(f2tf(x)); }

// mma.sync m16n8k8 tf32: D(16x8,f32) += A(16x8,tf32) * B(8x8,tf32)
__device__ __forceinline__ void mma8(float* d, uint32_t a0, uint32_t a1, uint32_t a2, uint32_t a3,
                                     uint32_t b0, uint32_t b1) {
    asm volatile("mma.sync.aligned.m16n8k8.row.col.f32.tf32.tf32.f32 "
                 "{%0,%1,%2,%3},{%4,%5,%6,%7},{%8,%9},{%0,%1,%2,%3};"
                 : "+f"(d[0]), "+f"(d[1]), "+f"(d[2]), "+f"(d[3])
                 : "r"(a0), "r"(a1), "r"(a2), "r"(a3), "r"(b0), "r"(b1));
}

__device__ __forceinline__ float rbff(float d, int k) {
    float mu = (float)k * GAPF;
    float v = d - mu;
    return __expf(-9.8f * v * v);
}
// softplus_bt(x, beta=0.5, thr=14)
__device__ __forceinline__ float sp_half(float x) {
    float t = 0.5f * x;
    if (t > 14.0f) return x;
    return 2.0f * (fmaxf(t, 0.0f) + __logf(1.0f + __expf(-fabsf(t))));
}

// ---------------- small per-atom kernels ----------------
__global__ void k_init_h(const int* __restrict__ at, const float* __restrict__ emb) {
    int idx = blockIdx.x * blockDim.x + threadIdx.x;
    if (idx < NA * DIM) g_h[idx] = emb[at[idx >> 6] * DIM + (idx & 63)];
}

__global__ void k_zero64() { g_nwsum[threadIdx.x] = 0.0f; }

__global__ void k_nw(const float* __restrict__ w1l) {
    __shared__ float hrow[DIM];
    int i = blockIdx.x, c = threadIdx.x;
    hrow[c] = g_h[i * DIM + c];
    __syncthreads();
    float s = 0.0f;
#pragma unroll
    for (int k = 0; k < DIM; k++) s += hrow[k] * w1l[k * DIM + c];
    g_nw[i * DIM + c]  = s;
    g_agg[i * DIM + c] = 0.0f;
    atomicAdd(&g_nwsum[c], s);
}

__global__ void k_update(const float* __restrict__ qw1l, const float* __restrict__ qb1l,
                         const float* __restrict__ qw2l, const float* __restrict__ qb2l,
                         const float* __restrict__ pb2l) {
    __shared__ float arow[DIM];
    __shared__ float trow[DIM];
    int i = blockIdx.x, c = threadIdx.x;
    // true agg = mma-accumulated part + pb2*(sum_i nw_i - nw_j)
    arow[c] = g_agg[i * DIM + c] + pb2l[c] * (g_nwsum[c] - g_nw[i * DIM + c]);
    __syncthreads();
    float s = qb1l[c];
#pragma unroll
    for (int k = 0; k < DIM; k++) s += arow[k] * qw1l[k * DIM + c];
    trow[c] = sp_half(s);
    __syncthreads();
    float s2 = qb2l[c];
#pragma unroll
    for (int k = 0; k < DIM; k++) s2 += trow[k] * qw2l[k * DIM + c];
    g_h[i * DIM + c] += s2;
}

__global__ void k_atom(const float* __restrict__ au_w1, const float* __restrict__ au_b1,
                       const float* __restrict__ au_w2, const float* __restrict__ au_b2) {
    __shared__ float hrow[DIM];
    __shared__ float red[DIM];
    int i = blockIdx.x, c = threadIdx.x;
    hrow[c] = g_h[i * DIM + c];
    __syncthreads();
    float s = au_b1[c];
#pragma unroll
    for (int k = 0; k < DIM; k++) s += hrow[k] * au_w1[k * DIM + c];
    float sp = (s > 20.0f) ? s : (fmaxf(s, 0.0f) + log1pf(__expf(-fabsf(s))));
    sp -= 0.69314718055994530942f;
    red[c] = sp * au_w2[c];
    __syncthreads();
    if (c < 32) {
        float v = red[c] + red[c + 32];
#pragma unroll
        for (int off = 16; off; off >>= 1) v += __shfl_down_sync(0xffffffffu, v, off);
        if (c == 0) g_ha[i] = v + au_b2[0];
    }
}

// ======================= fused conv via tensor cores =======================
// Block: 256 threads = 8 warps. Warp w owns 16 dst rows j = bx*128 + w*16 + r.
// Loop over 16 src atoms i (chunk = blockIdx.y). Per (warp,i):
//   GEMM1: u[16x64] = rbf[16x56] @ pw1[56x64] (+pb1 in accum init)
//   softplus -> t (row zeroed when i==j), staged through smem
//   GEMM2: acc[16x64] += t[16x64] @ (pw2[64x64] col-scaled by nw[i])
// acc atomically added to g_agg at the end.
#define TSTRIDE 68

__global__ void __launch_bounds__(256, 2)
k_conv(const float* __restrict__ dist,
       const float* __restrict__ pw1l, const float* __restrict__ pb1l,
       const float* __restrict__ pw2l) {
    extern __shared__ float sm[];
    float* s_pw1 = sm;                    // 56*64 (tf32-rounded, rows>=50 zero, swizzled)
    float* s_pw2 = sm + 3584;             // 64*64 (raw f32, swizzled)
    float* s_pb1 = sm + 7680;             // 64
    float* s_nw  = sm + 7744;             // 16*64 (this chunk's nw rows)
    float* s_tb  = sm + 8768;             // 8 warps * 16 * TSTRIDE

    int tid  = threadIdx.x;
    int warp = tid >> 5, lane = tid & 31;
    int g = lane >> 2, tq = lane & 3;
    int i0 = blockIdx.y * 16;

    for (int idx = tid; idx < 56 * 64; idx += 256) {
        int k = idx >> 6, n = idx & 63;
        float v = (k < 50) ? f2tf_f(pw1l[idx]) : 0.0f;
        s_pw1[(k << 6) + (n ^ ((k & 3) << 3))] = v;
    }
    for (int idx = tid; idx < 64 * 64; idx += 256) {
        int k = idx >> 6, n = idx & 63;
        s_pw2[(k << 6) + (n ^ ((k & 3) << 3))] = pw2l[idx];
    }
    if (tid < 64) s_pb1[tid] = pb1l[tid];
    for (int idx = tid; idx < 16 * 64; idx += 256) s_nw[idx] = g_nw[i0 * 64 + idx];
    __syncthreads();

    int jbase = blockIdx.x * 128 + warp * 16;
    int j0 = jbase + g;         // rows g   (frag c0,c1)
    int j1 = j0 + 8;            // rows g+8 (frag c2,c3)
    float* st = s_tb + warp * (16 * TSTRIDE);

    float acc[8][4];
#pragma unroll
    for (int nt = 0; nt < 8; nt++)
#pragma unroll
        for (int q = 0; q < 4; q++) acc[nt][q] = 0.0f;

#pragma unroll 1
    for (int ii = 0; ii < 16; ii++) {
        int i = i0 + ii;
        float d0 = (j0 == i) ? 0.0f : dist[i * NM1 + j0 - (j0 > i ? 1 : 0)];
        float d1 = (j1 == i) ? 0.0f : dist[i * NM1 + j1 - (j1 > i ? 1 : 0)];

        float rnw[8];
#pragma unroll
        for (int nt = 0; nt < 8; nt++) rnw[nt] = s_nw[ii * 64 + nt * 8 + g];

        // ---- GEMM1: u = rbf @ pw1 + pb1 ----
        float u[8][4];
#pragma unroll
        for (int nt = 0; nt < 8; nt++) {
            float2 pb = *(const float2*)&s_pb1[nt * 8 + 2 * tq];
            u[nt][0] = pb.x; u[nt][1] = pb.y; u[nt][2] = pb.x; u[nt][3] = pb.y;
        }
#pragma unroll
        for (int kk = 0; kk < 7; kk++) {
            int k0 = kk * 8 + tq;
            uint32_t a0 = f2tf(rbff(d0, k0));
            uint32_t a1 = f2tf(rbff(d1, k0));
            uint32_t a2 = f2tf(rbff(d0, k0 + 4));
            uint32_t a3 = f2tf(rbff(d1, k0 + 4));
#pragma unroll
            for (int nt = 0; nt < 8; nt++) {
                int nsw = (nt * 8 + g) ^ (tq << 3);
                uint32_t b0 = __float_as_uint(s_pw1[(k0 << 6) + nsw]);
                uint32_t b1 = __float_as_uint(s_pw1[((k0 + 4) << 6) + nsw]);
                mma8(u[nt], a0, a1, a2, a3, b0, b1);
            }
        }

        // ---- softplus, zero diag rows, stage t ----
        bool z0 = (j0 == i), z1 = (j1 == i);
        __syncwarp();
#pragma unroll
        for (int nt = 0; nt < 8; nt++) {
            int col = nt * 8 + 2 * tq;
            float2 r0 = make_float2(z0 ? 0.0f : sp_half(u[nt][0]),
                                    z0 ? 0.0f : sp_half(u[nt][1]));
            float2 r1 = make_float2(z1 ? 0.0f : sp_half(u[nt][2]),
                                    z1 ? 0.0f : sp_half(u[nt][3]));
            *(float2*)&st[g * TSTRIDE + col]       = r0;
            *(float2*)&st[(g + 8) * TSTRIDE + col] = r1;
        }
        __syncwarp();

        // ---- GEMM2: acc += t @ (pw2 col-scaled by nw[i]) ----
#pragma unroll
        for (int kk = 0; kk < 8; kk++) {
            int k0 = kk * 8 + tq;
            uint32_t a0 = f2tf(st[g * TSTRIDE + k0]);
            uint32_t a1 = f2tf(st[(g + 8) * TSTRIDE + k0]);
            uint32_t a2 = f2tf(st[g * TSTRIDE + k0 + 4]);
            uint32_t a3 = f2tf(st[(g + 8) * TSTRIDE + k0 + 4]);
#pragma unroll
            for (int nt = 0; nt < 8; nt++) {
                int nsw = (nt * 8 + g) ^ (tq << 3);
                uint32_t b0 = f2tf(s_pw2[(k0 << 6) + nsw] * rnw[nt]);
                uint32_t b1 = f2tf(s_pw2[((k0 + 4) << 6) + nsw] * rnw[nt]);
                mma8(acc[nt], a0, a1, a2, a3, b0, b1);
            }
        }
    }

#pragma unroll
    for (int nt = 0; nt < 8; nt++) {
        int col = nt * 8 + 2 * tq;
        atomicAdd(&g_agg[j0 * 64 + col],     acc[nt][0]);
        atomicAdd(&g_agg[j0 * 64 + col + 1], acc[nt][1]);
        atomicAdd(&g_agg[j1 * 64 + col],     acc[nt][2]);
        atomicAdd(&g_agg[j1 * 64 + col + 1], acc[nt][3]);
    }
}

// ======================= readout via tensor cores =======================
// Block: 256 threads = 8 warps, each warp 16 consecutive edges (block: 128).
// f[16x64] = b1 + ha_i*w1row0 + ha_j*w1row1 (accum init)  +  rbf[16x56] @ w1rows2..51
// then relu, 64x2 head, softmax.
__global__ void __launch_bounds__(256, 2)
k_readout(const float* __restrict__ dist,
          const float* __restrict__ ro_w1, const float* __restrict__ ro_b1,
          const float* __restrict__ ro_w2, const float* __restrict__ ro_b2,
          float* __restrict__ out) {
    __shared__ __align__(16) float s_wg[56 * 64];   // rbf-part weights, swizzled tf32
    __shared__ __align__(16) float s_wa[64];        // row 0 (ha_src)
    __shared__ __align__(16) float s_wb[64];        // row 1 (ha_dst)
    __shared__ __align__(16) float s_b1[64];
    __shared__ __align__(16) float s_w2[128];       // [64][2]
    __shared__ float s_b2[2];

    int tid  = threadIdx.x;
    int warp = tid >> 5, lane = tid & 31;
    int g = lane >> 2, tq = lane & 3;

    for (int idx = tid; idx < 56 * 64; idx += 256) {
        int k = idx >> 6, n = idx & 63;
        float v = (k < 50) ? f2tf_f(ro_w1[(2 + k) * 64 + n]) : 0.0f;
        s_wg[(k << 6) + (n ^ ((k & 3) << 3))] = v;
    }
    if (tid < 64)  { s_wa[tid] = ro_w1[tid]; s_wb[tid] = ro_w1[64 + tid]; s_b1[tid] = ro_b1[tid]; }
    if (tid < 128) s_w2[tid] = ro_w2[tid];
    if (tid < 2)   s_b2[tid] = ro_b2[tid];
    __syncthreads();

    int ebase = blockIdx.x * 128 + warp * 16;
    int e0 = ebase + g, e1 = e0 + 8;
    int i0a = e0 / NM1, p0 = e0 - i0a * NM1, j0a = p0 + (p0 >= i0a ? 1 : 0);
    int i1a = e1 / NM1, p1 = e1 - i1a * NM1, j1a = p1 + (p1 >= i1a ? 1 : 0);
    float hi0 = g_ha[i0a], hj0 = g_ha[j0a];
    float hi1 = g_ha[i1a], hj1 = g_ha[j1a];
    float d0 = dist[e0], d1 = dist[e1];

    float f[8][4];
#pragma unroll
    for (int nt = 0; nt < 8; nt++) {
        int col = nt * 8 + 2 * tq;
        float2 b  = *(const float2*)&s_b1[col];
        float2 wa = *(const float2*)&s_wa[col];
        float2 wb = *(const float2*)&s_wb[col];
        f[nt][0] = b.x + hi0 * wa.x + hj0 * wb.x;
        f[nt][1] = b.y + hi0 * wa.y + hj0 * wb.y;
        f[nt][2] = b.x + hi1 * wa.x + hj1 * wb.x;
        f[nt][3] = b.y + hi1 * wa.y + hj1 * wb.y;
    }
#pragma unroll
    for (int kk = 0; kk < 7; kk++) {
        int k0 = kk * 8 + tq;
        uint32_t a0 = f2tf(rbff(d0, k0));
        uint32_t a1 = f2tf(rbff(d1, k0));
        uint32_t a2 = f2tf(rbff(d0, k0 + 4));
        uint32_t a3 = f2tf(rbff(d1, k0 + 4));
#pragma unroll
        for (int nt = 0; nt < 8; nt++) {
            int nsw = (nt * 8 + g) ^ (tq << 3);
            uint32_t b0 = __float_as_uint(s_wg[(k0 << 6) + nsw]);
            uint32_t b1 = __float_as_uint(s_wg[((k0 + 4) << 6) + nsw]);
            mma8(f[nt], a0, a1, a2, a3, b0, b1);
        }
    }

    // epilogue: relu -> 64x2 head -> 4-lane reduce -> softmax
    float l00 = 0.0f, l01 = 0.0f, l10 = 0.0f, l11 = 0.0f;
#pragma unroll
    for (int nt = 0; nt < 8; nt++) {
        int col = nt * 8 + 2 * tq;
        float4 w = *(const float4*)&s_w2[col * 2];   // w2[col][0..1], w2[col+1][0..1]
        float v0 = fmaxf(f[nt][0], 0.0f), v1 = fmaxf(f[nt][1], 0.0f);
        float v2 = fmaxf(f[nt][2], 0.0f), v3 = fmaxf(f[nt][3], 0.0f);
        l00 += v0 * w.x + v1 * w.z;  l01 += v0 * w.y + v1 * w.w;
        l10 += v2 * w.x + v3 * w.z;  l11 += v2 * w.y + v3 * w.w;
    }
#pragma unroll
    for (int off = 1; off <= 2; off <<= 1) {
        l00 += __shfl_xor_sync(0xffffffffu, l00, off);
        l01 += __shfl_xor_sync(0xffffffffu, l01, off);
        l10 += __shfl_xor_sync(0xffffffffu, l10, off);
        l11 += __shfl_xor_sync(0xffffffffu, l11, off);
    }
    if (tq == 0) {
        float a = l00 + s_b2[0], b = l01 + s_b2[1];
        float m = fmaxf(a, b);
        float pa = __expf(a - m), pb = __expf(b - m);
        float inv = 1.0f / (pa + pb);
        *(float2*)&out[2 * e0] = make_float2(pa * inv, pb * inv);
        a = l10 + s_b2[0]; b = l11 + s_b2[1];
        m = fmaxf(a, b);
        pa = __expf(a - m); pb = __expf(b - m);
        inv = 1.0f / (pa + pb);
        *(float2*)&out[2 * e1] = make_float2(pa * inv, pb * inv);
    }
}

// ---------------- launch ------------------------------------------------------
extern "C" void kernel_launch(void* const* d_in, const int* in_sizes, int n_in,
                              void* d_out, int out_size) {
    const int*   at    = (const int*)  d_in[0];
    const float* dist  = (const float*)d_in[1];
    // d_in[2]=src, d_in[3]=dst implied by complete-graph closed form
    const float* emb   = (const float*)d_in[4];
    const float* w1    = (const float*)d_in[5];
    const float* pw1   = (const float*)d_in[6];
    const float* pb1   = (const float*)d_in[7];
    const float* pw2   = (const float*)d_in[8];
    const float* pb2   = (const float*)d_in[9];
    const float* qw1   = (const float*)d_in[10];
    const float* qb1   = (const float*)d_in[11];
    const float* qw2   = (const float*)d_in[12];
    const float* qb2   = (const float*)d_in[13];
    const float* au_w1 = (const float*)d_in[14];
    const float* au_b1 = (const float*)d_in[15];
    const float* au_w2 = (const float*)d_in[16];
    const float* au_b2 = (const float*)d_in[17];
    const float* ro_w1 = (const float*)d_in[18];
    const float* ro_b1 = (const float*)d_in[19];
    const float* ro_w2 = (const float*)d_in[20];
    const float* ro_b2 = (const float*)d_in[21];
    float* out = (float*)d_out;

    const int conv_smem = (3584 + 4096 + 64 + 1024 + 8 * 16 * TSTRIDE) * (int)sizeof(float);
    cudaFuncSetAttribute(k_conv, cudaFuncAttributeMaxDynamicSharedMemorySize, conv_smem);

    k_init_h<<<(NA * DIM + 255) / 256, 256>>>(at, emb);

    for (int l = 0; l < NCONV; l++) {
        k_zero64<<<1, 64>>>();
        k_nw<<<NA, DIM>>>(w1 + l * DIM * DIM);
        dim3 grid(NA / 128, 48);              // 6 x 48 blocks, i-chunk = 16
        k_conv<<<grid, 256, conv_smem>>>(dist, pw1 + l * 50 * DIM, pb1 + l * DIM,
                                         pw2 + l * DIM * DIM);
        k_update<<<NA, DIM>>>(qw1 + l * DIM * DIM, qb1 + l * DIM,
                              qw2 + l * DIM * DIM, qb2 + l * DIM,
                              pb2 + l * DIM);
    }
    k_atom<<<NA, DIM>>>(au_w1, au_b1, au_w2, au_b2);
    k_readout<<<NE / 128, 256>>>(dist, ro_w1, ro_b1, ro_w2, ro_b2, out);
}